// round 7
// baseline (speedup 1.0000x reference)
#include <cuda_runtime.h>
#include <cuda_bf16.h>
#include <cstdint>

#define NCOL 65536
#define NB 32
#define NPTS 2048

#define OFF1 0
#define OFF2 64
#define OFF3 192
#define OFFH1 1216
#define OFFH2 1728
#define OFFH3 1984
#define NSTAT 2112

#define WOFF_C2 0
#define WOFF_C3 32768
#define WOFF_H1 557056
#define WOFF_H2 688128
#define WOFF_H3 1212416
#define WPL_TOTAL 1343488

#define SMEMSZ 53248

// ---- scratch ----
__device__ float d_raw1[(size_t)NCOL * 64];
__device__ float d_raw2[(size_t)NCOL * 128];
__device__ float d_rawh1[(size_t)NCOL * 512];
__device__ float d_rawh2[(size_t)NCOL * 256];
__device__ float d_rawh3[(size_t)NCOL * 128];
__device__ __align__(16) char d_wpl[WPL_TOTAL];
__device__ float d_sum[NSTAT];
__device__ float d_sq[NSTAT];
__device__ unsigned d_gmax[NB * 1024];
__device__ float d_gbn[NB * 1024];
__device__ float d_hvec[NB * 512];
__device__ int d_nv[NB];

__device__ __forceinline__ uint32_t smem_u32(const void* p) {
    uint32_t a;
    asm("{ .reg .u64 t; cvta.to.shared.u64 t, %1; cvt.u32.u64 %0, t; }" : "=r"(a) : "l"(p));
    return a;
}
#define CP16(sa, ga) \
    asm volatile("cp.async.cg.shared.global [%0], [%1], 16;" ::"r"(sa), "l"(ga) : "memory")
#define CPC asm volatile("cp.async.commit_group;" ::: "memory")
#define CPW2 asm volatile("cp.async.wait_group 2;" ::: "memory")

__device__ __forceinline__ void mma16(float c[4], const uint32_t a[4], uint32_t b0,
                                      uint32_t b1) {
    asm volatile(
        "mma.sync.aligned.m16n8k16.row.col.f32.bf16.bf16.f32 "
        "{%0,%1,%2,%3}, {%4,%5,%6,%7}, {%8,%9}, {%0,%1,%2,%3};"
        : "+f"(c[0]), "+f"(c[1]), "+f"(c[2]), "+f"(c[3])
        : "r"(a[0]), "r"(a[1]), "r"(a[2]), "r"(a[3]), "r"(b0), "r"(b1));
}
__device__ __forceinline__ uint32_t packb(float lo_e, float hi_e) {
    __nv_bfloat162 h;
    h.x = __float2bfloat16_rn(lo_e);
    h.y = __float2bfloat16_rn(hi_e);
    return *(uint32_t*)&h;
}
__device__ __forceinline__ void split16_store(const float v[16], char* dhi, char* dlo,
                                              uint32_t swz) {
    uint32_t hw[8], lw[8];
#pragma unroll
    for (int tt = 0; tt < 4; tt++) {
        float v0 = v[2 * tt], v1 = v[2 * tt + 1];
        float v8 = v[2 * tt + 8], v9 = v[2 * tt + 9];
        float h0 = __bfloat162float(__float2bfloat16_rn(v0));
        float h1 = __bfloat162float(__float2bfloat16_rn(v1));
        float h8 = __bfloat162float(__float2bfloat16_rn(v8));
        float h9 = __bfloat162float(__float2bfloat16_rn(v9));
        hw[2 * tt] = packb(h0, h1);
        hw[2 * tt + 1] = packb(h8, h9);
        lw[2 * tt] = packb(v0 - h0, v1 - h1);
        lw[2 * tt + 1] = packb(v8 - h8, v9 - h9);
    }
    *(uint4*)(dhi + (0 ^ swz)) = make_uint4(hw[0], hw[1], hw[2], hw[3]);
    *(uint4*)(dhi + (16 ^ swz)) = make_uint4(hw[4], hw[5], hw[6], hw[7]);
    *(uint4*)(dlo + (0 ^ swz)) = make_uint4(lw[0], lw[1], lw[2], lw[3]);
    *(uint4*)(dlo + (16 ^ swz)) = make_uint4(lw[4], lw[5], lw[6], lw[7]);
}

// ===== prep: zero counters + split all weights into bf16 hi/lo planes =====
__global__ void prep_kernel(const float* __restrict__ w2, const float* __restrict__ w3,
                            const float* __restrict__ hw1, const float* __restrict__ hw2,
                            const float* __restrict__ hw3, char* __restrict__ dst) {
    int idx = blockIdx.x * 256 + threadIdx.x;  // 32768 threads
    if (idx < NSTAT) { d_sum[idx] = 0.f; d_sq[idx] = 0.f; }
    if (idx < NB * 1024) d_gmax[idx] = 0u;
    if (idx < NB) d_nv[idx] = 0;

    const float* W; int lda, woff, Cin; char* d; int li;
    if (idx < 512) { W = w2; lda = 64; woff = 0; Cin = 64; d = dst + WOFF_C2; li = idx; }
    else if (idx < 8704) { W = w3; lda = 128; woff = 0; Cin = 128; d = dst + WOFF_C3; li = idx - 512; }
    else if (idx < 10752) { W = hw1; lda = 1088; woff = 1024; Cin = 64; d = dst + WOFF_H1; li = idx - 8704; }
    else if (idx < 18944) { W = hw2; lda = 512; woff = 0; Cin = 512; d = dst + WOFF_H2; li = idx - 10752; }
    else if (idx < 20992) { W = hw3; lda = 256; woff = 0; Cin = 256; d = dst + WOFF_H3; li = idx - 18944; }
    else return;
    const int TK = Cin >> 4;
    const int m = li / TK, k16 = li % TK;
    const float* src = W + (size_t)m * lda + woff + k16 * 16;
    float v[16];
#pragma unroll
    for (int q = 0; q < 4; q++) {
        float4 f = *(const float4*)(src + q * 4);
        v[q * 4 + 0] = f.x; v[q * 4 + 1] = f.y; v[q * 4 + 2] = f.z; v[q * 4 + 3] = f.w;
    }
    const int row = m & 127;
    const uint32_t swz = ((row >> 2) & 1) * 16;
    char* base = d + (size_t)(((m >> 7) * TK + k16) * 2) * 4096 + row * 32;
    split16_store(v, base, base + 4096, swz);
}

// conv1: 3 -> 64, transposed out [col][64], fused stats
__global__ void conv1_kernel(const float* __restrict__ pts,
                             const float* __restrict__ w,
                             const float* __restrict__ b) {
    __shared__ float ws[192], bs[64], bsum[64], bsq[64];
    int tid = threadIdx.x;
    if (tid < 192) ws[tid] = w[tid];
    if (tid < 64) { bs[tid] = b[tid]; bsum[tid] = 0.f; bsq[tid] = 0.f; }
    __syncthreads();
    int wid = tid >> 5, lid = tid & 31;
    int colbase = (blockIdx.x * 8 + wid) * 32;
    int bb = colbase >> 11, n = colbase & 2047;
    const float* p = pts + (size_t)bb * 3 * NPTS + n + lid;
    float p0 = p[0], p1 = p[NPTS], p2 = p[2 * NPTS];
    float wa0 = ws[lid * 3], wa1 = ws[lid * 3 + 1], wa2 = ws[lid * 3 + 2];
    float wb0 = ws[(lid + 32) * 3], wb1 = ws[(lid + 32) * 3 + 1], wb2 = ws[(lid + 32) * 3 + 2];
    float ba = bs[lid], bbv = bs[lid + 32];
    float sa = 0.f, qa = 0.f, sb = 0.f, qb = 0.f;
#pragma unroll 8
    for (int c = 0; c < 32; c++) {
        float x = __shfl_sync(0xffffffffu, p0, c);
        float y = __shfl_sync(0xffffffffu, p1, c);
        float z = __shfl_sync(0xffffffffu, p2, c);
        float va = fmaf(wa0, x, fmaf(wa1, y, fmaf(wa2, z, ba)));
        float vb = fmaf(wb0, x, fmaf(wb1, y, fmaf(wb2, z, bbv)));
        d_raw1[(size_t)(colbase + c) * 64 + lid] = va;
        d_raw1[(size_t)(colbase + c) * 64 + 32 + lid] = vb;
        sa += va; qa = fmaf(va, va, qa);
        sb += vb; qb = fmaf(vb, vb, qb);
    }
    atomicAdd(&bsum[lid], sa); atomicAdd(&bsq[lid], qa);
    atomicAdd(&bsum[32 + lid], sb); atomicAdd(&bsq[32 + lid], qb);
    __syncthreads();
    if (tid < 64) {
        atomicAdd(&d_sum[OFF1 + tid], bsum[tid]);
        atomicAdd(&d_sq[OFF1 + tid], bsq[tid]);
    }
}

// ===== streaming bf16x3 GEMM, one m-chunk per CTA (grid.y = MC) =====
// smem: X ring @0 (2x8192), A ring @16384 (4x8192), sc @49152, sh @51200
// S (32x132 floats) overlays A ring during epilogue.
template <bool STORE, bool DOMAX, bool COLBIAS>
__global__ void __launch_bounds__(256, 2) mma_kernel(
    const char* __restrict__ wpl, const float* __restrict__ bias,
    const float* __restrict__ g, const float* __restrict__ be,
    const float* __restrict__ Xraw, int Cin, int actoff,
    float* __restrict__ Y, int statoff, int Mtot,
    const float* __restrict__ colbias) {
    extern __shared__ __align__(16) char smem[];
    float* sc_s = (float*)(smem + 49152);
    float* sh_s = (float*)(smem + 51200);
    float* S = (float*)(smem + 16384);
    const uint32_t aB = smem_u32(smem) + 16384;

    const int tid = threadIdx.x;
    const int wid = tid >> 5, lane = tid & 31;
    const int gq = lane >> 2, t4 = lane & 3;
    const int m0 = (wid & 3) * 32;
    const int n0 = (wid >> 2) * 64;
    const int col0 = blockIdx.x * 128;
    const int bb = col0 >> 11;
    const int TK = Cin >> 4;
    const int mc = blockIdx.y;

    // inline BN finalize of the input layer
    for (int k = tid; k < Cin; k += 256) {
        float m = d_sum[actoff + k] * (1.0f / NCOL);
        float v = d_sq[actoff + k] * (1.0f / NCOL) - m * m;
        float sc = g[k] * rsqrtf(v + 1e-5f);
        sc_s[k] = sc;
        sh_s[k] = fmaf(-m, sc, be[k]);
    }
    __syncthreads();

    const int row = tid & 127;
    const int grp = tid >> 7;
    const uint32_t swzr = ((row >> 2) & 1) * 16;
    const float* xsrc = Xraw + (size_t)(col0 + row) * Cin;
    const int xo1 = grp * 4, xo2 = grp * 4 + 8;
    const int rot = (wid & 3) * 2;

    float c[2][8][4];
#pragma unroll
    for (int i = 0; i < 2; i++)
#pragma unroll
        for (int j = 0; j < 8; j++)
#pragma unroll
            for (int k = 0; k < 4; k++) c[i][j][k] = 0.f;

    const char* gA = wpl + (size_t)mc * TK * 8192;
    {
        uint32_t s0 = aB + tid * 32;
        CP16(s0, gA + tid * 32); CP16(s0 + 16, gA + tid * 32 + 16); CPC;
        uint32_t s1 = aB + 8192 + tid * 32;
        CP16(s1, gA + 8192 + tid * 32); CP16(s1 + 16, gA + 8192 + tid * 32 + 16); CPC;
    }
    float4 px0 = *(const float4*)(xsrc + xo1);
    float4 px1 = *(const float4*)(xsrc + xo2);

    for (int t = 0; t < TK; t++) {
        {  // BN+relu+split+STS this k16 half-row into X ring
            float v[8];
            float4 sc0 = *(const float4*)(sc_s + t * 16 + xo1);
            float4 sh0 = *(const float4*)(sh_s + t * 16 + xo1);
            float4 sc1 = *(const float4*)(sc_s + t * 16 + xo2);
            float4 sh1 = *(const float4*)(sh_s + t * 16 + xo2);
            v[0] = fmaxf(fmaf(sc0.x, px0.x, sh0.x), 0.f);
            v[1] = fmaxf(fmaf(sc0.y, px0.y, sh0.y), 0.f);
            v[2] = fmaxf(fmaf(sc0.z, px0.z, sh0.z), 0.f);
            v[3] = fmaxf(fmaf(sc0.w, px0.w, sh0.w), 0.f);
            v[4] = fmaxf(fmaf(sc1.x, px1.x, sh1.x), 0.f);
            v[5] = fmaxf(fmaf(sc1.y, px1.y, sh1.y), 0.f);
            v[6] = fmaxf(fmaf(sc1.z, px1.z, sh1.z), 0.f);
            v[7] = fmaxf(fmaf(sc1.w, px1.w, sh1.w), 0.f);
            uint32_t hw[4], lw[4];
            float h0 = __bfloat162float(__float2bfloat16_rn(v[0]));
            float h1 = __bfloat162float(__float2bfloat16_rn(v[1]));
            float h4 = __bfloat162float(__float2bfloat16_rn(v[4]));
            float h5 = __bfloat162float(__float2bfloat16_rn(v[5]));
            float h2 = __bfloat162float(__float2bfloat16_rn(v[2]));
            float h3 = __bfloat162float(__float2bfloat16_rn(v[3]));
            float h6 = __bfloat162float(__float2bfloat16_rn(v[6]));
            float h7 = __bfloat162float(__float2bfloat16_rn(v[7]));
            hw[0] = packb(h0, h1); hw[1] = packb(h4, h5);
            hw[2] = packb(h2, h3); hw[3] = packb(h6, h7);
            lw[0] = packb(v[0] - h0, v[1] - h1); lw[1] = packb(v[4] - h4, v[5] - h5);
            lw[2] = packb(v[2] - h2, v[3] - h3); lw[3] = packb(v[6] - h6, v[7] - h7);
            char* dx = smem + (t & 1) * 8192 + row * 32;
            *(uint4*)(dx + ((grp * 16) ^ swzr)) = make_uint4(hw[0], hw[1], hw[2], hw[3]);
            *(uint4*)(dx + 4096 + ((grp * 16) ^ swzr)) = make_uint4(lw[0], lw[1], lw[2], lw[3]);
        }
        if (t + 2 < TK) {
            uint32_t sd = aB + ((t + 2) & 3) * 8192 + tid * 32;
            const char* gs = gA + (size_t)(t + 2) * 8192 + tid * 32;
            CP16(sd, gs); CP16(sd + 16, gs + 16);
        }
        CPC;
        if (t + 1 < TK) {
            px0 = *(const float4*)(xsrc + (t + 1) * 16 + xo1);
            px1 = *(const float4*)(xsrc + (t + 1) * 16 + xo2);
        }
        CPW2;
        __syncthreads();
        // ---- MMA on k16 t ----
        const char* ab = smem + 16384 + (t & 3) * 8192;
        const char* xb = smem + (t & 1) * 8192;
        uint32_t ah[2][4], al[2][4];
#pragma unroll
        for (int i = 0; i < 2; i++) {
            const int r1 = m0 + i * 16 + gq, r2 = r1 + 8;
            const uint32_t o1 = (uint32_t)r1 * 32 + ((t4 * 8) ^ (((r1 >> 2) & 1) * 16));
            const uint32_t o2 = (uint32_t)r2 * 32 + ((t4 * 8) ^ (((r2 >> 2) & 1) * 16));
            uint2 h1 = *(const uint2*)(ab + o1);
            uint2 h2 = *(const uint2*)(ab + o2);
            ah[i][0] = h1.x; ah[i][1] = h2.x; ah[i][2] = h1.y; ah[i][3] = h2.y;
            uint2 l1 = *(const uint2*)(ab + 4096 + o1);
            uint2 l2 = *(const uint2*)(ab + 4096 + o2);
            al[i][0] = l1.x; al[i][1] = l2.x; al[i][2] = l1.y; al[i][3] = l2.y;
        }
        // rotated, double-buffered j loop
        {
            const int rb0 = n0 + rot * 8 + gq;
            const uint32_t ob0 = (uint32_t)rb0 * 32 + ((t4 * 8) ^ (((rb0 >> 2) & 1) * 16));
            uint2 bh0 = *(const uint2*)(xb + ob0);
            uint2 bl0 = *(const uint2*)(xb + 4096 + ob0);
#pragma unroll
            for (int jj = 0; jj < 8; jj++) {
                uint2 bh1 = bh0, bl1 = bl0;
                if (jj < 7) {
                    const int jn = (jj + 1 + rot) & 7;
                    const int rbn = n0 + jn * 8 + gq;
                    const uint32_t obn =
                        (uint32_t)rbn * 32 + ((t4 * 8) ^ (((rbn >> 2) & 1) * 16));
                    bh1 = *(const uint2*)(xb + obn);
                    bl1 = *(const uint2*)(xb + 4096 + obn);
                }
                const int j = (jj + rot) & 7;
#pragma unroll
                for (int i = 0; i < 2; i++) {
                    mma16(c[i][j], ah[i], bl0.x, bl0.y);
                    mma16(c[i][j], al[i], bh0.x, bh0.y);
                    mma16(c[i][j], ah[i], bh0.x, bh0.y);
                }
                bh0 = bh1; bl0 = bl1;
            }
        }
    }

    // ---- epilogue: bias, stats (+max) ----
#pragma unroll
    for (int i = 0; i < 2; i++) {
        const int chA = mc * 128 + m0 + i * 16 + gq;
        const int chB = chA + 8;
        const float bvA = COLBIAS ? colbias[bb * Mtot + chA] : bias[chA];
        const float bvB = COLBIAS ? colbias[bb * Mtot + chB] : bias[chB];
        float sA = 0.f, qA = 0.f, sB = 0.f, qB = 0.f;
        float mA = -3.4e38f, mB = -3.4e38f;
#pragma unroll
        for (int j = 0; j < 8; j++) {
            c[i][j][0] += bvA; c[i][j][1] += bvA;
            c[i][j][2] += bvB; c[i][j][3] += bvB;
            sA += c[i][j][0] + c[i][j][1];
            qA = fmaf(c[i][j][0], c[i][j][0], qA);
            qA = fmaf(c[i][j][1], c[i][j][1], qA);
            sB += c[i][j][2] + c[i][j][3];
            qB = fmaf(c[i][j][2], c[i][j][2], qB);
            qB = fmaf(c[i][j][3], c[i][j][3], qB);
            if (DOMAX) {
                mA = fmaxf(mA, fmaxf(c[i][j][0], c[i][j][1]));
                mB = fmaxf(mB, fmaxf(c[i][j][2], c[i][j][3]));
            }
        }
#pragma unroll
        for (int o = 1; o <= 2; o <<= 1) {
            sA += __shfl_xor_sync(0xffffffffu, sA, o);
            qA += __shfl_xor_sync(0xffffffffu, qA, o);
            sB += __shfl_xor_sync(0xffffffffu, sB, o);
            qB += __shfl_xor_sync(0xffffffffu, qB, o);
            if (DOMAX) {
                mA = fmaxf(mA, __shfl_xor_sync(0xffffffffu, mA, o));
                mB = fmaxf(mB, __shfl_xor_sync(0xffffffffu, mB, o));
            }
        }
        if (t4 == 0) {
            atomicAdd(&d_sum[statoff + chA], sA);
            atomicAdd(&d_sq[statoff + chA], qA);
            atomicAdd(&d_sum[statoff + chB], sB);
            atomicAdd(&d_sq[statoff + chB], qB);
            if (DOMAX) {
                unsigned uA = __float_as_uint(mA);
                uA = (uA >> 31) ? ~uA : (uA | 0x80000000u);
                atomicMax(&d_gmax[bb * Mtot + chA], uA);
                unsigned uB = __float_as_uint(mB);
                uB = (uB >> 31) ? ~uB : (uB | 0x80000000u);
                atomicMax(&d_gmax[bb * Mtot + chB], uB);
            }
        }
    }

    if (STORE) {  // 32-col slabs through S (overlays A ring)
#pragma unroll
        for (int s = 0; s < 4; s++) {
            __syncthreads();
            if ((wid >> 2) == (s >> 1)) {
                const int jb = (s & 1) * 4;
#pragma unroll
                for (int i = 0; i < 2; i++)
#pragma unroll
                    for (int jj = 0; jj < 4; jj++) {
                        const int j = jb + jj;
                        const int lc = j * 8 + t4 * 2 - (s & 1) * 32;
                        const int chl = m0 + i * 16 + gq;
                        S[lc * 132 + chl] = c[i][j][0];
                        S[(lc + 1) * 132 + chl] = c[i][j][1];
                        S[lc * 132 + chl + 8] = c[i][j][2];
                        S[(lc + 1) * 132 + chl + 8] = c[i][j][3];
                    }
            }
            __syncthreads();
            const int lcol = tid >> 3;
            const int cg2 = (tid & 7) * 16;
            float* yp = Y + (size_t)(col0 + s * 32 + lcol) * Mtot + mc * 128 + cg2;
            const float* sp = S + lcol * 132 + cg2;
#pragma unroll
            for (int q = 0; q < 4; q++)
                *(float4*)(yp + q * 4) = *(const float4*)(sp + q * 4);
        }
    }
}

// decode max + inline conv3 BN finalize
__global__ void gbn_kernel(const float* __restrict__ g, const float* __restrict__ be) {
    int i = blockIdx.x * 256 + threadIdx.x;
    unsigned u = d_gmax[i];
    float f = (u >> 31) ? __uint_as_float(u & 0x7FFFFFFFu) : __uint_as_float(~u);
    int c = i & 1023;
    float m = d_sum[OFF3 + c] * (1.0f / NCOL);
    float v = d_sq[OFF3 + c] * (1.0f / NCOL) - m * m;
    float sc = g[c] * rsqrtf(v + 1e-5f);
    d_gbn[i] = fmaf(sc, f, fmaf(-m, sc, be[c]));
}

__global__ void hvec_kernel(const float* __restrict__ w1, const float* __restrict__ b1) {
    int bbk = blockIdx.x;
    int oc = blockIdx.y * 128 + threadIdx.x;
    __shared__ float gb[1024];
    for (int i = threadIdx.x; i < 1024; i += 128) gb[i] = d_gbn[bbk * 1024 + i];
    __syncthreads();
    float a = b1[oc];
    const float* wr = w1 + (size_t)oc * 1088;
#pragma unroll 4
    for (int k = 0; k < 1024; k++) a = fmaf(wr[k], gb[k], a);
    d_hvec[bbk * 512 + oc] = a;
}

// h4 with inline h3 BN finalize
__global__ void h4_kernel(const float* __restrict__ w4, const float* __restrict__ b4,
                          const float* __restrict__ g, const float* __restrict__ be,
                          float* __restrict__ out) {
    __shared__ float ws[128], scs[128], shs[128];
    __shared__ int vcnt;
    int tid = threadIdx.x;
    if (tid < 128) {
        ws[tid] = w4[tid];
        float m = d_sum[OFFH3 + tid] * (1.0f / NCOL);
        float v = d_sq[OFFH3 + tid] * (1.0f / NCOL) - m * m;
        float sc = g[tid] * rsqrtf(v + 1e-5f);
        scs[tid] = sc;
        shs[tid] = fmaf(-m, sc, be[tid]);
    }
    if (tid == 0) vcnt = 0;
    __syncthreads();
    int wid = tid >> 5, lid = tid & 31;
    int col = blockIdx.x * 8 + wid;
    const float* src = d_rawh3 + (size_t)col * 128;
    float a = 0.f;
#pragma unroll
    for (int c = 0; c < 4; c++) {
        int k = c * 32 + lid;
        float v = src[k];
        a = fmaf(ws[k], fmaxf(fmaf(scs[k], v, shs[k]), 0.f), a);
    }
#pragma unroll
    for (int o = 16; o >= 1; o >>= 1) a += __shfl_xor_sync(0xffffffffu, a, o);
    if (lid == 0) {
        float wv = 1.f + a + __ldg(b4);
        out[96 + col] = wv;
        if (wv > 1e-4f) atomicAdd(&vcnt, 1);
    }
    __syncthreads();
    if (tid == 0) atomicAdd(&d_nv[(blockIdx.x * 8) >> 11], vcnt);
}

__global__ void solve_kernel(const float* __restrict__ pts, float* __restrict__ out) {
    int bbk = blockIdx.x;
    const float* w = out + 96 + bbk * NPTS;
    const float* px = pts + (size_t)bbk * 3 * NPTS;
    bool usew = d_nv[bbk] > 3;
    float acc[9];
#pragma unroll
    for (int k = 0; k < 9; k++) acc[k] = 0.f;
    for (int n = threadIdx.x; n < NPTS; n += 256) {
        float wv = w[n];
        float we = usew ? ((wv > 1e-4f) ? wv : 0.f) : 1.f;
        float x = px[n], y = px[NPTS + n], z = px[2 * NPTS + n];
        acc[0] = fmaf(we * x, x, acc[0]);
        acc[1] = fmaf(we * x, y, acc[1]);
        acc[2] += we * x;
        acc[3] = fmaf(we * y, y, acc[3]);
        acc[4] += we * y;
        acc[5] += we;
        acc[6] = fmaf(we * x, z, acc[6]);
        acc[7] = fmaf(we * y, z, acc[7]);
        acc[8] = fmaf(we, z, acc[8]);
    }
#pragma unroll
    for (int k = 0; k < 9; k++)
#pragma unroll
        for (int o = 16; o >= 1; o >>= 1) acc[k] += __shfl_xor_sync(0xffffffffu, acc[k], o);
    __shared__ float red[8][9];
    int wid = threadIdx.x >> 5, lane = threadIdx.x & 31;
    if (lane == 0)
        for (int k = 0; k < 9; k++) red[wid][k] = acc[k];
    __syncthreads();
    if (threadIdx.x == 0) {
        float a[9];
        for (int k = 0; k < 9; k++) {
            float s = 0.f;
            for (int i = 0; i < 8; i++) s += red[i][k];
            a[k] = s;
        }
        float L11 = sqrtf(a[0]);
        float L21 = a[1] / L11, L31 = a[2] / L11;
        float L22 = sqrtf(a[3] - L21 * L21);
        float L32 = (a[4] - L31 * L21) / L22;
        float L33 = sqrtf(a[5] - L31 * L31 - L32 * L32);
        float y1 = a[6] / L11;
        float y2 = (a[7] - L21 * y1) / L22;
        float y3 = (a[8] - L31 * y1 - L32 * y2) / L33;
        float be3 = y3 / L33;
        float be2 = (y2 - L32 * be3) / L22;
        float be1 = (y1 - L21 * be2 - L31 * be3) / L11;
        out[bbk * 3 + 0] = be1;
        out[bbk * 3 + 1] = be2;
        out[bbk * 3 + 2] = be3;
    }
}

// ================= launch =================
extern "C" void kernel_launch(void* const* d_in, const int* in_sizes, int n_in,
                              void* d_out, int out_size) {
    const float* pts = (const float*)d_in[0];
    const float* e_w1 = (const float*)d_in[1];
    const float* e_b1 = (const float*)d_in[2];
    const float* e_g1 = (const float*)d_in[3];
    const float* e_be1 = (const float*)d_in[4];
    const float* e_w2 = (const float*)d_in[5];
    const float* e_b2 = (const float*)d_in[6];
    const float* e_g2 = (const float*)d_in[7];
    const float* e_be2 = (const float*)d_in[8];
    const float* e_w3 = (const float*)d_in[9];
    const float* e_b3 = (const float*)d_in[10];
    const float* e_g3 = (const float*)d_in[11];
    const float* e_be3 = (const float*)d_in[12];
    const float* h_w1 = (const float*)d_in[13];
    const float* h_b1 = (const float*)d_in[14];
    const float* h_g1 = (const float*)d_in[15];
    const float* h_be1 = (const float*)d_in[16];
    const float* h_w2 = (const float*)d_in[17];
    const float* h_b2 = (const float*)d_in[18];
    const float* h_g2 = (const float*)d_in[19];
    const float* h_be2 = (const float*)d_in[20];
    const float* h_w3 = (const float*)d_in[21];
    const float* h_b3 = (const float*)d_in[22];
    const float* h_g3 = (const float*)d_in[23];
    const float* h_be3 = (const float*)d_in[24];
    const float* h_w4 = (const float*)d_in[25];
    const float* h_b4 = (const float*)d_in[26];
    float* out = (float*)d_out;

    float *p_raw1, *p_raw2, *p_rawh1, *p_rawh2, *p_rawh3, *p_hvec;
    char* p_wpl;
    cudaGetSymbolAddress((void**)&p_raw1, d_raw1);
    cudaGetSymbolAddress((void**)&p_raw2, d_raw2);
    cudaGetSymbolAddress((void**)&p_rawh1, d_rawh1);
    cudaGetSymbolAddress((void**)&p_rawh2, d_rawh2);
    cudaGetSymbolAddress((void**)&p_rawh3, d_rawh3);
    cudaGetSymbolAddress((void**)&p_hvec, d_hvec);
    cudaGetSymbolAddress((void**)&p_wpl, d_wpl);

    cudaFuncSetAttribute(mma_kernel<true, false, false>,
                         cudaFuncAttributeMaxDynamicSharedMemorySize, SMEMSZ);
    cudaFuncSetAttribute(mma_kernel<false, true, false>,
                         cudaFuncAttributeMaxDynamicSharedMemorySize, SMEMSZ);
    cudaFuncSetAttribute(mma_kernel<true, false, true>,
                         cudaFuncAttributeMaxDynamicSharedMemorySize, SMEMSZ);

    prep_kernel<<<128, 256>>>(e_w2, e_w3, h_w1, h_w2, h_w3, p_wpl);
    conv1_kernel<<<256, 256>>>(pts, e_w1, e_b1);
    // conv2: 128 x 65536 x 64
    mma_kernel<true, false, false><<<dim3(512, 1), 256, SMEMSZ>>>(
        p_wpl + WOFF_C2, e_b2, e_g1, e_be1, p_raw1, 64, OFF1, p_raw2, OFF2, 128, nullptr);
    // conv3: 1024 x 65536 x 128 (stats+max only)
    mma_kernel<false, true, false><<<dim3(512, 8), 256, SMEMSZ>>>(
        p_wpl + WOFF_C3, e_b3, e_g2, e_be2, p_raw2, 128, OFF2, nullptr, OFF3, 1024, nullptr);
    gbn_kernel<<<128, 256>>>(e_g3, e_be3);
    hvec_kernel<<<dim3(32, 4), 128>>>(h_w1, h_b1);
    // h1 (pointfeat): 512 x 65536 x 64, colbias
    mma_kernel<true, false, true><<<dim3(512, 4), 256, SMEMSZ>>>(
        p_wpl + WOFF_H1, h_b1, e_g1, e_be1, p_raw1, 64, OFF1, p_rawh1, OFFH1, 512, p_hvec);
    // h2: 256 x 65536 x 512
    mma_kernel<true, false, false><<<dim3(512, 2), 256, SMEMSZ>>>(
        p_wpl + WOFF_H2, h_b2, h_g1, h_be1, p_rawh1, 512, OFFH1, p_rawh2, OFFH2, 256, nullptr);
    // h3: 128 x 65536 x 256
    mma_kernel<true, false, false><<<dim3(512, 1), 256, SMEMSZ>>>(
        p_wpl + WOFF_H3, h_b3, h_g2, h_be2, p_rawh2, 256, OFFH2, p_rawh3, OFFH3, 128, nullptr);
    h4_kernel<<<8192, 256>>>(h_w4, h_b4, h_g3, h_be3, out);
    solve_kernel<<<32, 256>>>(pts, out);
}

// round 8
// speedup vs baseline: 2.0084x; 2.0084x over previous
#include <cuda_runtime.h>
#include <cuda_bf16.h>
#include <cstdint>

#define NCOL 65536
#define NB 32
#define NPTS 2048

#define OFF1 0
#define OFF2 64
#define OFF3 192
#define OFFH1 1216
#define OFFH2 1728
#define OFFH3 1984
#define NSTAT 2112

#define WOFF_C2 0
#define WOFF_C3 32768
#define WOFF_H1 557056
#define WOFF_H2 688128
#define WOFF_H3 1212416
#define WPL_TOTAL 1343488

// ---- scratch ----
__device__ float d_raw1[(size_t)NCOL * 64];
__device__ float d_raw2[(size_t)NCOL * 128];
__device__ float d_rawh1[(size_t)NCOL * 512];
__device__ float d_rawh2[(size_t)NCOL * 256];
__device__ float d_rawh3[(size_t)NCOL * 128];
__device__ __align__(16) char d_wpl[WPL_TOTAL];
__device__ float d_sum[NSTAT];
__device__ float d_sq[NSTAT];
__device__ unsigned d_gmax[NB * 1024];
__device__ float d_gbn[NB * 1024];
__device__ float d_hvec[NB * 512];
__device__ int d_nv[NB];

__device__ __forceinline__ uint32_t smem_u32(const void* p) {
    uint32_t a;
    asm("{ .reg .u64 t; cvta.to.shared.u64 t, %1; cvt.u32.u64 %0, t; }" : "=r"(a) : "l"(p));
    return a;
}
#define CP16(sa, ga) \
    asm volatile("cp.async.cg.shared.global [%0], [%1], 16;" ::"r"(sa), "l"(ga) : "memory")
#define CPC asm volatile("cp.async.commit_group;" ::: "memory")
#define CPW2 asm volatile("cp.async.wait_group 2;" ::: "memory")

__device__ __forceinline__ void mma16(float c[4], const uint32_t a[4], uint32_t b0,
                                      uint32_t b1) {
    asm volatile(
        "mma.sync.aligned.m16n8k16.row.col.f32.bf16.bf16.f32 "
        "{%0,%1,%2,%3}, {%4,%5,%6,%7}, {%8,%9}, {%0,%1,%2,%3};"
        : "+f"(c[0]), "+f"(c[1]), "+f"(c[2]), "+f"(c[3])
        : "r"(a[0]), "r"(a[1]), "r"(a[2]), "r"(a[3]), "r"(b0), "r"(b1));
}
__device__ __forceinline__ uint32_t packb(float lo_e, float hi_e) {
    __nv_bfloat162 h;
    h.x = __float2bfloat16_rn(lo_e);
    h.y = __float2bfloat16_rn(hi_e);
    return *(uint32_t*)&h;
}
__device__ __forceinline__ void split16_store(const float v[16], char* dhi, char* dlo,
                                              uint32_t swz) {
    uint32_t hw[8], lw[8];
#pragma unroll
    for (int tt = 0; tt < 4; tt++) {
        float v0 = v[2 * tt], v1 = v[2 * tt + 1];
        float v8 = v[2 * tt + 8], v9 = v[2 * tt + 9];
        float h0 = __bfloat162float(__float2bfloat16_rn(v0));
        float h1 = __bfloat162float(__float2bfloat16_rn(v1));
        float h8 = __bfloat162float(__float2bfloat16_rn(v8));
        float h9 = __bfloat162float(__float2bfloat16_rn(v9));
        hw[2 * tt] = packb(h0, h1);
        hw[2 * tt + 1] = packb(h8, h9);
        lw[2 * tt] = packb(v0 - h0, v1 - h1);
        lw[2 * tt + 1] = packb(v8 - h8, v9 - h9);
    }
    *(uint4*)(dhi + (0 ^ swz)) = make_uint4(hw[0], hw[1], hw[2], hw[3]);
    *(uint4*)(dhi + (16 ^ swz)) = make_uint4(hw[4], hw[5], hw[6], hw[7]);
    *(uint4*)(dlo + (0 ^ swz)) = make_uint4(lw[0], lw[1], lw[2], lw[3]);
    *(uint4*)(dlo + (16 ^ swz)) = make_uint4(lw[4], lw[5], lw[6], lw[7]);
}

// ===== prep: zero counters + split all weights into bf16 hi/lo planes =====
__global__ void prep_kernel(const float* __restrict__ w2, const float* __restrict__ w3,
                            const float* __restrict__ hw1, const float* __restrict__ hw2,
                            const float* __restrict__ hw3, char* __restrict__ dst) {
    int idx = blockIdx.x * 256 + threadIdx.x;  // 32768 threads
    if (idx < NSTAT) { d_sum[idx] = 0.f; d_sq[idx] = 0.f; }
    if (idx < NB * 1024) d_gmax[idx] = 0u;
    if (idx < NB) d_nv[idx] = 0;

    const float* W; int lda, woff, Cin; char* d; int li;
    if (idx < 512) { W = w2; lda = 64; woff = 0; Cin = 64; d = dst + WOFF_C2; li = idx; }
    else if (idx < 8704) { W = w3; lda = 128; woff = 0; Cin = 128; d = dst + WOFF_C3; li = idx - 512; }
    else if (idx < 10752) { W = hw1; lda = 1088; woff = 1024; Cin = 64; d = dst + WOFF_H1; li = idx - 8704; }
    else if (idx < 18944) { W = hw2; lda = 512; woff = 0; Cin = 512; d = dst + WOFF_H2; li = idx - 10752; }
    else if (idx < 20992) { W = hw3; lda = 256; woff = 0; Cin = 256; d = dst + WOFF_H3; li = idx - 18944; }
    else return;
    const int TK = Cin >> 4;
    const int m = li / TK, k16 = li % TK;
    const float* src = W + (size_t)m * lda + woff + k16 * 16;
    float v[16];
#pragma unroll
    for (int q = 0; q < 4; q++) {
        float4 f = *(const float4*)(src + q * 4);
        v[q * 4 + 0] = f.x; v[q * 4 + 1] = f.y; v[q * 4 + 2] = f.z; v[q * 4 + 3] = f.w;
    }
    const int row = m & 127;
    const uint32_t swz = ((row >> 2) & 1) * 16;
    char* base = d + (size_t)(((m >> 7) * TK + k16) * 2) * 4096 + row * 32;
    split16_store(v, base, base + 4096, swz);
}

// conv1: 3 -> 64, transposed out [col][64], fused stats
__global__ void conv1_kernel(const float* __restrict__ pts,
                             const float* __restrict__ w,
                             const float* __restrict__ b) {
    __shared__ float ws[192], bs[64], bsum[64], bsq[64];
    int tid = threadIdx.x;
    if (tid < 192) ws[tid] = w[tid];
    if (tid < 64) { bs[tid] = b[tid]; bsum[tid] = 0.f; bsq[tid] = 0.f; }
    __syncthreads();
    int wid = tid >> 5, lid = tid & 31;
    int colbase = (blockIdx.x * 8 + wid) * 32;
    int bb = colbase >> 11, n = colbase & 2047;
    const float* p = pts + (size_t)bb * 3 * NPTS + n + lid;
    float p0 = p[0], p1 = p[NPTS], p2 = p[2 * NPTS];
    float wa0 = ws[lid * 3], wa1 = ws[lid * 3 + 1], wa2 = ws[lid * 3 + 2];
    float wb0 = ws[(lid + 32) * 3], wb1 = ws[(lid + 32) * 3 + 1], wb2 = ws[(lid + 32) * 3 + 2];
    float ba = bs[lid], bbv = bs[lid + 32];
    float sa = 0.f, qa = 0.f, sb = 0.f, qb = 0.f;
#pragma unroll 8
    for (int c = 0; c < 32; c++) {
        float x = __shfl_sync(0xffffffffu, p0, c);
        float y = __shfl_sync(0xffffffffu, p1, c);
        float z = __shfl_sync(0xffffffffu, p2, c);
        float va = fmaf(wa0, x, fmaf(wa1, y, fmaf(wa2, z, ba)));
        float vb = fmaf(wb0, x, fmaf(wb1, y, fmaf(wb2, z, bbv)));
        d_raw1[(size_t)(colbase + c) * 64 + lid] = va;
        d_raw1[(size_t)(colbase + c) * 64 + 32 + lid] = vb;
        sa += va; qa = fmaf(va, va, qa);
        sb += vb; qb = fmaf(vb, vb, qb);
    }
    atomicAdd(&bsum[lid], sa); atomicAdd(&bsq[lid], qa);
    atomicAdd(&bsum[32 + lid], sb); atomicAdd(&bsq[32 + lid], qb);
    __syncthreads();
    if (tid < 64) {
        atomicAdd(&d_sum[OFF1 + tid], bsum[tid]);
        atomicAdd(&d_sq[OFF1 + tid], bsq[tid]);
    }
}

// ================= pipelined bf16x3 HMMA GEMM (R6 structure) =================
// XRES: X planes resident @0 (TK*8192), A ring @AOFF (4x8192), sc/sh @AOFF+32768.
// streaming: X ring @0 (2x8192), A ring @16384, sc/sh @49152.
// S (32x132 floats) overlays the A ring during epilogue.
template <bool XRES, bool STORE, bool DOMAX, bool COLBIAS>
__global__ void __launch_bounds__(256, 2) mma_kernel(
    const char* __restrict__ wpl, const float* __restrict__ bias,
    const float* __restrict__ g, const float* __restrict__ be,
    const float* __restrict__ Xraw, int Cin, int actoff,
    float* __restrict__ Y, int statoff, int Mtot,
    const float* __restrict__ colbias) {
    extern __shared__ __align__(16) char smem[];
    const int tid = threadIdx.x;
    const int wid = tid >> 5, lane = tid & 31;
    const int gq = lane >> 2, t4 = lane & 3;
    const int m0 = (wid & 3) * 32;
    const int n0 = (wid >> 2) * 64;
    const int col0 = blockIdx.x * 128;
    const int bb = col0 >> 11;
    const int TK = Cin >> 4, MC = Mtot >> 7;
    const int AOFF = XRES ? (TK * 8192) : 16384;
    const uint32_t aB = smem_u32(smem) + AOFF;
    float* S = (float*)(smem + AOFF);
    float* sc_s = (float*)(smem + AOFF + 32768);
    float* sh_s = sc_s + Cin;

    // inline BN finalize of the input layer
    for (int k = tid; k < Cin; k += 256) {
        float m = d_sum[actoff + k] * (1.0f / NCOL);
        float v = d_sq[actoff + k] * (1.0f / NCOL) - m * m;
        float sc = g[k] * rsqrtf(v + 1e-5f);
        sc_s[k] = sc;
        sh_s[k] = fmaf(-m, sc, be[k]);
    }
    __syncthreads();

    const int row = tid & 127;
    const int grp = tid >> 7;
    const uint32_t swzr = ((row >> 2) & 1) * 16;

    if (XRES) {  // convert ALL X once into resident planes
        for (int k16 = grp; k16 < TK; k16 += 2) {
            const float* src = Xraw + (size_t)(col0 + row) * Cin + k16 * 16;
            float v[16];
#pragma unroll
            for (int q = 0; q < 4; q++) {
                float4 f = *(const float4*)(src + q * 4);
                float4 sc = *(const float4*)(sc_s + k16 * 16 + q * 4);
                float4 sh = *(const float4*)(sh_s + k16 * 16 + q * 4);
                v[q * 4 + 0] = fmaxf(fmaf(sc.x, f.x, sh.x), 0.f);
                v[q * 4 + 1] = fmaxf(fmaf(sc.y, f.y, sh.y), 0.f);
                v[q * 4 + 2] = fmaxf(fmaf(sc.z, f.z, sh.z), 0.f);
                v[q * 4 + 3] = fmaxf(fmaf(sc.w, f.w, sh.w), 0.f);
            }
            char* dh = smem + k16 * 8192 + row * 32;
            split16_store(v, dh, dh + 4096, swzr);
        }
    }

    const float* xsrc = Xraw + (size_t)(col0 + row) * Cin;
    const int xo1 = grp * 4, xo2 = grp * 4 + 8;

    for (int mc = 0; mc < MC; mc++) {
        __syncthreads();  // covers XRES conversion / prev epilogue S reads
        float c[2][8][4];
#pragma unroll
        for (int i = 0; i < 2; i++)
#pragma unroll
            for (int j = 0; j < 8; j++)
#pragma unroll
                for (int k = 0; k < 4; k++) c[i][j][k] = 0.f;

        const char* gA = wpl + (size_t)mc * TK * 8192;
        {
            uint32_t s0 = aB + tid * 32;
            CP16(s0, gA + tid * 32); CP16(s0 + 16, gA + tid * 32 + 16); CPC;
            uint32_t s1 = aB + 8192 + tid * 32;
            CP16(s1, gA + 8192 + tid * 32); CP16(s1 + 16, gA + 8192 + tid * 32 + 16); CPC;
        }
        float4 px0, px1;
        if (!XRES) { px0 = *(const float4*)(xsrc + xo1); px1 = *(const float4*)(xsrc + xo2); }

        for (int t = 0; t < TK; t++) {
            if (!XRES) {  // BN+relu+split+STS this k16 half-row into X ring
                float v[8];
                float4 sc0 = *(const float4*)(sc_s + t * 16 + xo1);
                float4 sh0 = *(const float4*)(sh_s + t * 16 + xo1);
                float4 sc1 = *(const float4*)(sc_s + t * 16 + xo2);
                float4 sh1 = *(const float4*)(sh_s + t * 16 + xo2);
                v[0] = fmaxf(fmaf(sc0.x, px0.x, sh0.x), 0.f);
                v[1] = fmaxf(fmaf(sc0.y, px0.y, sh0.y), 0.f);
                v[2] = fmaxf(fmaf(sc0.z, px0.z, sh0.z), 0.f);
                v[3] = fmaxf(fmaf(sc0.w, px0.w, sh0.w), 0.f);
                v[4] = fmaxf(fmaf(sc1.x, px1.x, sh1.x), 0.f);
                v[5] = fmaxf(fmaf(sc1.y, px1.y, sh1.y), 0.f);
                v[6] = fmaxf(fmaf(sc1.z, px1.z, sh1.z), 0.f);
                v[7] = fmaxf(fmaf(sc1.w, px1.w, sh1.w), 0.f);
                uint32_t hw[4], lw[4];
                float h0 = __bfloat162float(__float2bfloat16_rn(v[0]));
                float h1 = __bfloat162float(__float2bfloat16_rn(v[1]));
                float h4 = __bfloat162float(__float2bfloat16_rn(v[4]));
                float h5 = __bfloat162float(__float2bfloat16_rn(v[5]));
                float h2 = __bfloat162float(__float2bfloat16_rn(v[2]));
                float h3 = __bfloat162float(__float2bfloat16_rn(v[3]));
                float h6 = __bfloat162float(__float2bfloat16_rn(v[6]));
                float h7 = __bfloat162float(__float2bfloat16_rn(v[7]));
                hw[0] = packb(h0, h1); hw[1] = packb(h4, h5);
                hw[2] = packb(h2, h3); hw[3] = packb(h6, h7);
                lw[0] = packb(v[0] - h0, v[1] - h1); lw[1] = packb(v[4] - h4, v[5] - h5);
                lw[2] = packb(v[2] - h2, v[3] - h3); lw[3] = packb(v[6] - h6, v[7] - h7);
                char* dx = smem + (t & 1) * 8192 + row * 32;
                *(uint4*)(dx + ((grp * 16) ^ swzr)) = make_uint4(hw[0], hw[1], hw[2], hw[3]);
                *(uint4*)(dx + 4096 + ((grp * 16) ^ swzr)) = make_uint4(lw[0], lw[1], lw[2], lw[3]);
            }
            if (t + 2 < TK) {
                uint32_t sd = aB + ((t + 2) & 3) * 8192 + tid * 32;
                const char* gs = gA + (size_t)(t + 2) * 8192 + tid * 32;
                CP16(sd, gs); CP16(sd + 16, gs + 16);
            }
            CPC;
            if (!XRES && t + 1 < TK) {
                px0 = *(const float4*)(xsrc + (t + 1) * 16 + xo1);
                px1 = *(const float4*)(xsrc + (t + 1) * 16 + xo2);
            }
            CPW2;
            __syncthreads();
            // ---- MMA on k16 t ----
            const char* ab = smem + AOFF + (t & 3) * 8192;
            const char* xb = XRES ? (smem + t * 8192) : (smem + (t & 1) * 8192);
            uint32_t ah[2][4], al[2][4];
#pragma unroll
            for (int i = 0; i < 2; i++) {
                const int r1 = m0 + i * 16 + gq, r2 = r1 + 8;
                const uint32_t o1 = (uint32_t)r1 * 32 + ((t4 * 8) ^ (((r1 >> 2) & 1) * 16));
                const uint32_t o2 = (uint32_t)r2 * 32 + ((t4 * 8) ^ (((r2 >> 2) & 1) * 16));
                uint2 h1 = *(const uint2*)(ab + o1);
                uint2 h2 = *(const uint2*)(ab + o2);
                ah[i][0] = h1.x; ah[i][1] = h2.x; ah[i][2] = h1.y; ah[i][3] = h2.y;
                uint2 l1 = *(const uint2*)(ab + 4096 + o1);
                uint2 l2 = *(const uint2*)(ab + 4096 + o2);
                al[i][0] = l1.x; al[i][1] = l2.x; al[i][2] = l1.y; al[i][3] = l2.y;
            }
            // double-buffered j loop (B frag prefetch, no rotation)
            {
                const int rb0 = n0 + gq;
                const uint32_t ob0 = (uint32_t)rb0 * 32 + ((t4 * 8) ^ (((rb0 >> 2) & 1) * 16));
                uint2 bh0 = *(const uint2*)(xb + ob0);
                uint2 bl0 = *(const uint2*)(xb + 4096 + ob0);
#pragma unroll
                for (int j = 0; j < 8; j++) {
                    uint2 bh1 = bh0, bl1 = bl0;
                    if (j < 7) {
                        const int rbn = n0 + (j + 1) * 8 + gq;
                        const uint32_t obn =
                            (uint32_t)rbn * 32 + ((t4 * 8) ^ (((rbn >> 2) & 1) * 16));
                        bh1 = *(const uint2*)(xb + obn);
                        bl1 = *(const uint2*)(xb + 4096 + obn);
                    }
#pragma unroll
                    for (int i = 0; i < 2; i++) {
                        mma16(c[i][j], ah[i], bl0.x, bl0.y);
                        mma16(c[i][j], al[i], bh0.x, bh0.y);
                        mma16(c[i][j], ah[i], bh0.x, bh0.y);
                    }
                    bh0 = bh1; bl0 = bl1;
                }
            }
        }

        // ---- epilogue: bias, stats (+max) ----
#pragma unroll
        for (int i = 0; i < 2; i++) {
            const int chA = mc * 128 + m0 + i * 16 + gq;
            const int chB = chA + 8;
            const float bvA = COLBIAS ? colbias[bb * Mtot + chA] : bias[chA];
            const float bvB = COLBIAS ? colbias[bb * Mtot + chB] : bias[chB];
            float sA = 0.f, qA = 0.f, sB = 0.f, qB = 0.f;
            float mA = -3.4e38f, mB = -3.4e38f;
#pragma unroll
            for (int j = 0; j < 8; j++) {
                c[i][j][0] += bvA; c[i][j][1] += bvA;
                c[i][j][2] += bvB; c[i][j][3] += bvB;
                sA += c[i][j][0] + c[i][j][1];
                qA = fmaf(c[i][j][0], c[i][j][0], qA);
                qA = fmaf(c[i][j][1], c[i][j][1], qA);
                sB += c[i][j][2] + c[i][j][3];
                qB = fmaf(c[i][j][2], c[i][j][2], qB);
                qB = fmaf(c[i][j][3], c[i][j][3], qB);
                if (DOMAX) {
                    mA = fmaxf(mA, fmaxf(c[i][j][0], c[i][j][1]));
                    mB = fmaxf(mB, fmaxf(c[i][j][2], c[i][j][3]));
                }
            }
#pragma unroll
            for (int o = 1; o <= 2; o <<= 1) {
                sA += __shfl_xor_sync(0xffffffffu, sA, o);
                qA += __shfl_xor_sync(0xffffffffu, qA, o);
                sB += __shfl_xor_sync(0xffffffffu, sB, o);
                qB += __shfl_xor_sync(0xffffffffu, qB, o);
                if (DOMAX) {
                    mA = fmaxf(mA, __shfl_xor_sync(0xffffffffu, mA, o));
                    mB = fmaxf(mB, __shfl_xor_sync(0xffffffffu, mB, o));
                }
            }
            if (t4 == 0) {
                atomicAdd(&d_sum[statoff + chA], sA);
                atomicAdd(&d_sq[statoff + chA], qA);
                atomicAdd(&d_sum[statoff + chB], sB);
                atomicAdd(&d_sq[statoff + chB], qB);
                if (DOMAX) {
                    unsigned uA = __float_as_uint(mA);
                    uA = (uA >> 31) ? ~uA : (uA | 0x80000000u);
                    atomicMax(&d_gmax[bb * Mtot + chA], uA);
                    unsigned uB = __float_as_uint(mB);
                    uB = (uB >> 31) ? ~uB : (uB | 0x80000000u);
                    atomicMax(&d_gmax[bb * Mtot + chB], uB);
                }
            }
        }

        if (STORE) {  // 32-col slabs through S (overlays A ring)
#pragma unroll
            for (int s = 0; s < 4; s++) {
                __syncthreads();
                if ((wid >> 2) == (s >> 1)) {
                    const int jb = (s & 1) * 4;
#pragma unroll
                    for (int i = 0; i < 2; i++)
#pragma unroll
                        for (int jj = 0; jj < 4; jj++) {
                            const int j = jb + jj;
                            const int lc = j * 8 + t4 * 2 - (s & 1) * 32;
                            const int chl = m0 + i * 16 + gq;
                            S[lc * 132 + chl] = c[i][j][0];
                            S[(lc + 1) * 132 + chl] = c[i][j][1];
                            S[lc * 132 + chl + 8] = c[i][j][2];
                            S[(lc + 1) * 132 + chl + 8] = c[i][j][3];
                        }
                }
                __syncthreads();
                const int lcol = tid >> 3;
                const int cg2 = (tid & 7) * 16;
                float* yp = Y + (size_t)(col0 + s * 32 + lcol) * Mtot + mc * 128 + cg2;
                const float* sp = S + lcol * 132 + cg2;
#pragma unroll
                for (int q = 0; q < 4; q++)
                    *(float4*)(yp + q * 4) = *(const float4*)(sp + q * 4);
            }
        }
    }
}

// decode max + inline conv3 BN finalize
__global__ void gbn_kernel(const float* __restrict__ g, const float* __restrict__ be) {
    int i = blockIdx.x * 256 + threadIdx.x;
    unsigned u = d_gmax[i];
    float f = (u >> 31) ? __uint_as_float(u & 0x7FFFFFFFu) : __uint_as_float(~u);
    int c = i & 1023;
    float m = d_sum[OFF3 + c] * (1.0f / NCOL);
    float v = d_sq[OFF3 + c] * (1.0f / NCOL) - m * m;
    float sc = g[c] * rsqrtf(v + 1e-5f);
    d_gbn[i] = fmaf(sc, f, fmaf(-m, sc, be[c]));
}

__global__ void hvec_kernel(const float* __restrict__ w1, const float* __restrict__ b1) {
    int bbk = blockIdx.x;
    int oc = blockIdx.y * 128 + threadIdx.x;
    __shared__ float gb[1024];
    for (int i = threadIdx.x; i < 1024; i += 128) gb[i] = d_gbn[bbk * 1024 + i];
    __syncthreads();
    float a = b1[oc];
    const float* wr = w1 + (size_t)oc * 1088;
#pragma unroll 4
    for (int k = 0; k < 1024; k++) a = fmaf(wr[k], gb[k], a);
    d_hvec[bbk * 512 + oc] = a;
}

// h4 with inline h3 BN finalize
__global__ void h4_kernel(const float* __restrict__ w4, const float* __restrict__ b4,
                          const float* __restrict__ g, const float* __restrict__ be,
                          float* __restrict__ out) {
    __shared__ float ws[128], scs[128], shs[128];
    __shared__ int vcnt;
    int tid = threadIdx.x;
    if (tid < 128) {
        ws[tid] = w4[tid];
        float m = d_sum[OFFH3 + tid] * (1.0f / NCOL);
        float v = d_sq[OFFH3 + tid] * (1.0f / NCOL) - m * m;
        float sc = g[tid] * rsqrtf(v + 1e-5f);
        scs[tid] = sc;
        shs[tid] = fmaf(-m, sc, be[tid]);
    }
    if (tid == 0) vcnt = 0;
    __syncthreads();
    int wid = tid >> 5, lid = tid & 31;
    int col = blockIdx.x * 8 + wid;
    const float* src = d_rawh3 + (size_t)col * 128;
    float a = 0.f;
#pragma unroll
    for (int c = 0; c < 4; c++) {
        int k = c * 32 + lid;
        float v = src[k];
        a = fmaf(ws[k], fmaxf(fmaf(scs[k], v, shs[k]), 0.f), a);
    }
#pragma unroll
    for (int o = 16; o >= 1; o >>= 1) a += __shfl_xor_sync(0xffffffffu, a, o);
    if (lid == 0) {
        float wv = 1.f + a + __ldg(b4);
        out[96 + col] = wv;
        if (wv > 1e-4f) atomicAdd(&vcnt, 1);
    }
    __syncthreads();
    if (tid == 0) atomicAdd(&d_nv[(blockIdx.x * 8) >> 11], vcnt);
}

__global__ void solve_kernel(const float* __restrict__ pts, float* __restrict__ out) {
    int bbk = blockIdx.x;
    const float* w = out + 96 + bbk * NPTS;
    const float* px = pts + (size_t)bbk * 3 * NPTS;
    bool usew = d_nv[bbk] > 3;
    float acc[9];
#pragma unroll
    for (int k = 0; k < 9; k++) acc[k] = 0.f;
    for (int n = threadIdx.x; n < NPTS; n += 256) {
        float wv = w[n];
        float we = usew ? ((wv > 1e-4f) ? wv : 0.f) : 1.f;
        float x = px[n], y = px[NPTS + n], z = px[2 * NPTS + n];
        acc[0] = fmaf(we * x, x, acc[0]);
        acc[1] = fmaf(we * x, y, acc[1]);
        acc[2] += we * x;
        acc[3] = fmaf(we * y, y, acc[3]);
        acc[4] += we * y;
        acc[5] += we;
        acc[6] = fmaf(we * x, z, acc[6]);
        acc[7] = fmaf(we * y, z, acc[7]);
        acc[8] = fmaf(we, z, acc[8]);
    }
#pragma unroll
    for (int k = 0; k < 9; k++)
#pragma unroll
        for (int o = 16; o >= 1; o >>= 1) acc[k] += __shfl_xor_sync(0xffffffffu, acc[k], o);
    __shared__ float red[8][9];
    int wid = threadIdx.x >> 5, lane = threadIdx.x & 31;
    if (lane == 0)
        for (int k = 0; k < 9; k++) red[wid][k] = acc[k];
    __syncthreads();
    if (threadIdx.x == 0) {
        float a[9];
        for (int k = 0; k < 9; k++) {
            float s = 0.f;
            for (int i = 0; i < 8; i++) s += red[i][k];
            a[k] = s;
        }
        float L11 = sqrtf(a[0]);
        float L21 = a[1] / L11, L31 = a[2] / L11;
        float L22 = sqrtf(a[3] - L21 * L21);
        float L32 = (a[4] - L31 * L21) / L22;
        float L33 = sqrtf(a[5] - L31 * L31 - L32 * L32);
        float y1 = a[6] / L11;
        float y2 = (a[7] - L21 * y1) / L22;
        float y3 = (a[8] - L31 * y1 - L32 * y2) / L33;
        float be3 = y3 / L33;
        float be2 = (y2 - L32 * be3) / L22;
        float be1 = (y1 - L21 * be2 - L31 * be3) / L11;
        out[bbk * 3 + 0] = be1;
        out[bbk * 3 + 1] = be2;
        out[bbk * 3 + 2] = be3;
    }
}

// ================= launch =================
extern "C" void kernel_launch(void* const* d_in, const int* in_sizes, int n_in,
                              void* d_out, int out_size) {
    const float* pts = (const float*)d_in[0];
    const float* e_w1 = (const float*)d_in[1];
    const float* e_b1 = (const float*)d_in[2];
    const float* e_g1 = (const float*)d_in[3];
    const float* e_be1 = (const float*)d_in[4];
    const float* e_w2 = (const float*)d_in[5];
    const float* e_b2 = (const float*)d_in[6];
    const float* e_g2 = (const float*)d_in[7];
    const float* e_be2 = (const float*)d_in[8];
    const float* e_w3 = (const float*)d_in[9];
    const float* e_b3 = (const float*)d_in[10];
    const float* e_g3 = (const float*)d_in[11];
    const float* e_be3 = (const float*)d_in[12];
    const float* h_w1 = (const float*)d_in[13];
    const float* h_b1 = (const float*)d_in[14];
    const float* h_g1 = (const float*)d_in[15];
    const float* h_be1 = (const float*)d_in[16];
    const float* h_w2 = (const float*)d_in[17];
    const float* h_b2 = (const float*)d_in[18];
    const float* h_g2 = (const float*)d_in[19];
    const float* h_be2 = (const float*)d_in[20];
    const float* h_w3 = (const float*)d_in[21];
    const float* h_b3 = (const float*)d_in[22];
    const float* h_g3 = (const float*)d_in[23];
    const float* h_be3 = (const float*)d_in[24];
    const float* h_w4 = (const float*)d_in[25];
    const float* h_b4 = (const float*)d_in[26];
    float* out = (float*)d_out;

    float *p_raw1, *p_raw2, *p_rawh1, *p_rawh2, *p_rawh3, *p_hvec;
    char* p_wpl;
    cudaGetSymbolAddress((void**)&p_raw1, d_raw1);
    cudaGetSymbolAddress((void**)&p_raw2, d_raw2);
    cudaGetSymbolAddress((void**)&p_rawh1, d_rawh1);
    cudaGetSymbolAddress((void**)&p_rawh2, d_rawh2);
    cudaGetSymbolAddress((void**)&p_rawh3, d_rawh3);
    cudaGetSymbolAddress((void**)&p_hvec, d_hvec);
    cudaGetSymbolAddress((void**)&p_wpl, d_wpl);

    // dynamic smem: XRES = TK*8192 + 32768 + 8*Cin ; streaming = 49152 + 8*Cin
    cudaFuncSetAttribute(mma_kernel<true, true, false, false>,
                         cudaFuncAttributeMaxDynamicSharedMemorySize, 66048);
    cudaFuncSetAttribute(mma_kernel<true, false, true, false>,
                         cudaFuncAttributeMaxDynamicSharedMemorySize, 99328);
    cudaFuncSetAttribute(mma_kernel<true, true, false, true>,
                         cudaFuncAttributeMaxDynamicSharedMemorySize, 66048);
    cudaFuncSetAttribute(mma_kernel<false, true, false, false>,
                         cudaFuncAttributeMaxDynamicSharedMemorySize, 53248);

    prep_kernel<<<128, 256>>>(e_w2, e_w3, h_w1, h_w2, h_w3, p_wpl);
    conv1_kernel<<<256, 256>>>(pts, e_w1, e_b1);
    // conv2: 128 x 65536 x 64 (XRES)
    mma_kernel<true, true, false, false><<<512, 256, 66048>>>(
        p_wpl + WOFF_C2, e_b2, e_g1, e_be1, p_raw1, 64, OFF1, p_raw2, OFF2, 128, nullptr);
    // conv3: 1024 x 65536 x 128 (XRES, stats+max only)
    mma_kernel<true, false, true, false><<<512, 256, 99328>>>(
        p_wpl + WOFF_C3, e_b3, e_g2, e_be2, p_raw2, 128, OFF2, nullptr, OFF3, 1024, nullptr);
    gbn_kernel<<<128, 256>>>(e_g3, e_be3);
    hvec_kernel<<<dim3(32, 4), 128>>>(h_w1, h_b1);
    // h1 (pointfeat): 512 x 65536 x 64 (XRES, colbias)
    mma_kernel<true, true, false, true><<<512, 256, 66048>>>(
        p_wpl + WOFF_H1, h_b1, e_g1, e_be1, p_raw1, 64, OFF1, p_rawh1, OFFH1, 512, p_hvec);
    // h2: 256 x 65536 x 512 (streaming)
    mma_kernel<false, true, false, false><<<512, 256, 53248>>>(
        p_wpl + WOFF_H2, h_b2, h_g1, h_be1, p_rawh1, 512, OFFH1, p_rawh2, OFFH2, 256, nullptr);
    // h3: 128 x 65536 x 256 (streaming)
    mma_kernel<false, true, false, false><<<512, 256, 51200>>>(
        p_wpl + WOFF_H3, h_b3, h_g2, h_be2, p_rawh2, 256, OFFH2, p_rawh3, OFFH3, 128, nullptr);
    h4_kernel<<<8192, 256>>>(h_w4, h_b4, h_g3, h_be3, out);
    solve_kernel<<<32, 256>>>(pts, out);
}

// round 9
// speedup vs baseline: 2.0194x; 1.0055x over previous
#include <cuda_runtime.h>
#include <cuda_bf16.h>
#include <cstdint>

#define NCOL 65536
#define NB 32
#define NPTS 2048

#define OFF1 0
#define OFF2 64
#define OFF3 192
#define OFFH1 1216
#define OFFH2 1728
#define OFFH3 1984
#define NSTAT 2112

#define WOFF_C2 0
#define WOFF_C3 32768
#define WOFF_H1 557056
#define WOFF_H2 688128
#define WOFF_H3 1212416
#define WPL_TOTAL 1343488

// ---- scratch ----
__device__ float d_raw1[(size_t)NCOL * 64];
__device__ float d_raw2[(size_t)NCOL * 128];
__device__ float d_rawh1[(size_t)NCOL * 512];
__device__ float d_rawh2[(size_t)NCOL * 256];
__device__ float d_rawh3[(size_t)NCOL * 128];
__device__ __align__(16) char d_wpl[WPL_TOTAL];
__device__ float d_sum[NSTAT];
__device__ float d_sq[NSTAT];
__device__ unsigned d_gmax[NB * 1024];
__device__ float d_gbn[NB * 1024];
__device__ float d_hvec[NB * 512];
__device__ int d_nv[NB];

__device__ __forceinline__ uint32_t smem_u32(const void* p) {
    uint32_t a;
    asm("{ .reg .u64 t; cvta.to.shared.u64 t, %1; cvt.u32.u64 %0, t; }" : "=r"(a) : "l"(p));
    return a;
}
#define CP16(sa, ga) \
    asm volatile("cp.async.cg.shared.global [%0], [%1], 16;" ::"r"(sa), "l"(ga) : "memory")
#define CPC asm volatile("cp.async.commit_group;" ::: "memory")
#define CPW2 asm volatile("cp.async.wait_group 2;" ::: "memory")

__device__ __forceinline__ void mma16(float c[4], const uint32_t a[4], uint32_t b0,
                                      uint32_t b1) {
    asm volatile(
        "mma.sync.aligned.m16n8k16.row.col.f32.bf16.bf16.f32 "
        "{%0,%1,%2,%3}, {%4,%5,%6,%7}, {%8,%9}, {%0,%1,%2,%3};"
        : "+f"(c[0]), "+f"(c[1]), "+f"(c[2]), "+f"(c[3])
        : "r"(a[0]), "r"(a[1]), "r"(a[2]), "r"(a[3]), "r"(b0), "r"(b1));
}
__device__ __forceinline__ uint32_t packb(float lo_e, float hi_e) {
    __nv_bfloat162 h;
    h.x = __float2bfloat16_rn(lo_e);
    h.y = __float2bfloat16_rn(hi_e);
    return *(uint32_t*)&h;
}
// merged hi/lo chunk layout: row = 64B, 4 chunks of 16B = {hi(2t,2t+1), hi(2t+8,2t+9),
// lo(2t,2t+1), lo(2t+8,2t+9)}, chunk position swizzled by (row>>1)&3.
__device__ __forceinline__ void split16_merged(const float v[16], char* rowbase, int swz3) {
#pragma unroll
    for (int t = 0; t < 4; t++) {
        float a0 = v[2 * t], a1 = v[2 * t + 1];
        float a8 = v[2 * t + 8], a9 = v[2 * t + 9];
        float h0 = __bfloat162float(__float2bfloat16_rn(a0));
        float h1 = __bfloat162float(__float2bfloat16_rn(a1));
        float h8 = __bfloat162float(__float2bfloat16_rn(a8));
        float h9 = __bfloat162float(__float2bfloat16_rn(a9));
        uint4 u = make_uint4(packb(h0, h1), packb(h8, h9),
                             packb(a0 - h0, a1 - h1), packb(a8 - h8, a9 - h9));
        *(uint4*)(rowbase + ((t ^ swz3) << 4)) = u;
    }
}

// ===== prep: zero counters + split all weights into merged bf16 planes =====
__global__ void prep_kernel(const float* __restrict__ w2, const float* __restrict__ w3,
                            const float* __restrict__ hw1, const float* __restrict__ hw2,
                            const float* __restrict__ hw3, char* __restrict__ dst) {
    int idx = blockIdx.x * 256 + threadIdx.x;
    if (idx < NSTAT) { d_sum[idx] = 0.f; d_sq[idx] = 0.f; }
    if (idx < NB * 1024) d_gmax[idx] = 0u;
    if (idx < NB) d_nv[idx] = 0;

    const float* W; int lda, woff, Cin; char* d; int li;
    if (idx < 512) { W = w2; lda = 64; woff = 0; Cin = 64; d = dst + WOFF_C2; li = idx; }
    else if (idx < 8704) { W = w3; lda = 128; woff = 0; Cin = 128; d = dst + WOFF_C3; li = idx - 512; }
    else if (idx < 10752) { W = hw1; lda = 1088; woff = 1024; Cin = 64; d = dst + WOFF_H1; li = idx - 8704; }
    else if (idx < 18944) { W = hw2; lda = 512; woff = 0; Cin = 512; d = dst + WOFF_H2; li = idx - 10752; }
    else if (idx < 20992) { W = hw3; lda = 256; woff = 0; Cin = 256; d = dst + WOFF_H3; li = idx - 18944; }
    else return;
    const int TK = Cin >> 4;
    const int m = li / TK, k16 = li % TK;
    const float* src = W + (size_t)m * lda + woff + k16 * 16;
    float v[16];
#pragma unroll
    for (int q = 0; q < 4; q++) {
        float4 f = *(const float4*)(src + q * 4);
        v[q * 4 + 0] = f.x; v[q * 4 + 1] = f.y; v[q * 4 + 2] = f.z; v[q * 4 + 3] = f.w;
    }
    const int row = m & 127;
    char* base = d + (size_t)((m >> 7) * TK + k16) * 8192 + row * 64;
    split16_merged(v, base, (row >> 1) & 3);
}

// conv1: 3 -> 64, transposed out [col][64], fused stats
__global__ void conv1_kernel(const float* __restrict__ pts,
                             const float* __restrict__ w,
                             const float* __restrict__ b) {
    __shared__ float ws[192], bs[64], bsum[64], bsq[64];
    int tid = threadIdx.x;
    if (tid < 192) ws[tid] = w[tid];
    if (tid < 64) { bs[tid] = b[tid]; bsum[tid] = 0.f; bsq[tid] = 0.f; }
    __syncthreads();
    int wid = tid >> 5, lid = tid & 31;
    int colbase = (blockIdx.x * 8 + wid) * 32;
    int bb = colbase >> 11, n = colbase & 2047;
    const float* p = pts + (size_t)bb * 3 * NPTS + n + lid;
    float p0 = p[0], p1 = p[NPTS], p2 = p[2 * NPTS];
    float wa0 = ws[lid * 3], wa1 = ws[lid * 3 + 1], wa2 = ws[lid * 3 + 2];
    float wb0 = ws[(lid + 32) * 3], wb1 = ws[(lid + 32) * 3 + 1], wb2 = ws[(lid + 32) * 3 + 2];
    float ba = bs[lid], bbv = bs[lid + 32];
    float sa = 0.f, qa = 0.f, sb = 0.f, qb = 0.f;
#pragma unroll 8
    for (int c = 0; c < 32; c++) {
        float x = __shfl_sync(0xffffffffu, p0, c);
        float y = __shfl_sync(0xffffffffu, p1, c);
        float z = __shfl_sync(0xffffffffu, p2, c);
        float va = fmaf(wa0, x, fmaf(wa1, y, fmaf(wa2, z, ba)));
        float vb = fmaf(wb0, x, fmaf(wb1, y, fmaf(wb2, z, bbv)));
        d_raw1[(size_t)(colbase + c) * 64 + lid] = va;
        d_raw1[(size_t)(colbase + c) * 64 + 32 + lid] = vb;
        sa += va; qa = fmaf(va, va, qa);
        sb += vb; qb = fmaf(vb, vb, qb);
    }
    atomicAdd(&bsum[lid], sa); atomicAdd(&bsq[lid], qa);
    atomicAdd(&bsum[32 + lid], sb); atomicAdd(&bsq[32 + lid], qb);
    __syncthreads();
    if (tid < 64) {
        atomicAdd(&d_sum[OFF1 + tid], bsum[tid]);
        atomicAdd(&d_sq[OFF1 + tid], bsq[tid]);
    }
}

// ================= pipelined bf16x3 HMMA GEMM (merged layout) =================
template <bool XRES, bool STORE, bool DOMAX, bool COLBIAS, int TK, int MC>
__global__ void __launch_bounds__(256, 2) mma_kernel(
    const char* __restrict__ wpl, const float* __restrict__ bias,
    const float* __restrict__ g, const float* __restrict__ be,
    const float* __restrict__ Xraw, int actoff,
    float* __restrict__ Y, int statoff,
    const float* __restrict__ colbias) {
    extern __shared__ __align__(16) char smem[];
    constexpr int Cin = TK * 16;
    constexpr int Mtot = MC * 128;
    constexpr int AOFF = XRES ? (TK * 8192) : 16384;
    const int tid = threadIdx.x;
    const int wid = tid >> 5, lane = tid & 31;
    const int gq = lane >> 2, t4 = lane & 3;
    const int m0 = (wid & 3) * 32;
    const int n0 = (wid >> 2) * 64;
    const int col0 = blockIdx.x * 128;
    const int bb = col0 >> 11;
    const uint32_t aB = smem_u32(smem) + AOFF;
    float* S = (float*)(smem + AOFF);
    float* sc_s = (float*)(smem + AOFF + 32768);
    float* sh_s = sc_s + Cin;

    // inline BN finalize of the input layer
    for (int k = tid; k < Cin; k += 256) {
        float m = d_sum[actoff + k] * (1.0f / NCOL);
        float v = d_sq[actoff + k] * (1.0f / NCOL) - m * m;
        float sc = g[k] * rsqrtf(v + 1e-5f);
        sc_s[k] = sc;
        sh_s[k] = fmaf(-m, sc, be[k]);
    }
    __syncthreads();

    const int row = tid & 127;
    const int grp = tid >> 7;

    if (XRES) {  // convert ALL X once into resident merged blocks
        for (int k16 = grp; k16 < TK; k16 += 2) {
            const float* src = Xraw + (size_t)(col0 + row) * Cin + k16 * 16;
            float v[16];
#pragma unroll
            for (int q = 0; q < 4; q++) {
                float4 f = *(const float4*)(src + q * 4);
                float4 sc = *(const float4*)(sc_s + k16 * 16 + q * 4);
                float4 sh = *(const float4*)(sh_s + k16 * 16 + q * 4);
                v[q * 4 + 0] = fmaxf(fmaf(sc.x, f.x, sh.x), 0.f);
                v[q * 4 + 1] = fmaxf(fmaf(sc.y, f.y, sh.y), 0.f);
                v[q * 4 + 2] = fmaxf(fmaf(sc.z, f.z, sh.z), 0.f);
                v[q * 4 + 3] = fmaxf(fmaf(sc.w, f.w, sh.w), 0.f);
            }
            split16_merged(v, smem + k16 * 8192 + row * 64, (row >> 1) & 3);
        }
    }

    const float* xsrc = Xraw + (size_t)(col0 + row) * Cin;
    const int xo1 = grp * 4, xo2 = grp * 4 + 8;

    // hoisted fragment byte offsets (loop-invariant)
    uint32_t aoA[2][2], boB[8];
#pragma unroll
    for (int i = 0; i < 2; i++) {
        const int r1 = m0 + i * 16 + gq, r2 = r1 + 8;
        aoA[i][0] = r1 * 64 + ((t4 ^ ((r1 >> 1) & 3)) << 4);
        aoA[i][1] = r2 * 64 + ((t4 ^ ((r2 >> 1) & 3)) << 4);
    }
#pragma unroll
    for (int j = 0; j < 8; j++) {
        const int rb = n0 + j * 8 + gq;
        boB[j] = rb * 64 + ((t4 ^ ((rb >> 1) & 3)) << 4);
    }

    for (int mc = 0; mc < MC; mc++) {
        __syncthreads();  // covers XRES conversion / prev epilogue S reads
        float c[2][8][4];
#pragma unroll
        for (int i = 0; i < 2; i++)
#pragma unroll
            for (int j = 0; j < 8; j++)
#pragma unroll
                for (int k = 0; k < 4; k++) c[i][j][k] = 0.f;

        const char* gA = wpl + (size_t)mc * TK * 8192;
        {
            uint32_t s0 = aB + tid * 32;
            CP16(s0, gA + tid * 32); CP16(s0 + 16, gA + tid * 32 + 16); CPC;
            uint32_t s1 = aB + 8192 + tid * 32;
            CP16(s1, gA + 8192 + tid * 32); CP16(s1 + 16, gA + 8192 + tid * 32 + 16); CPC;
        }
        float4 px0, px1;
        if (!XRES) { px0 = *(const float4*)(xsrc + xo1); px1 = *(const float4*)(xsrc + xo2); }

        for (int t = 0; t < TK; t++) {
            if (!XRES) {  // BN+relu+split into merged X ring (2 chunks per thread)
                float v[8];
                float4 sc0 = *(const float4*)(sc_s + t * 16 + xo1);
                float4 sh0 = *(const float4*)(sh_s + t * 16 + xo1);
                float4 sc1 = *(const float4*)(sc_s + t * 16 + xo2);
                float4 sh1 = *(const float4*)(sh_s + t * 16 + xo2);
                v[0] = fmaxf(fmaf(sc0.x, px0.x, sh0.x), 0.f);
                v[1] = fmaxf(fmaf(sc0.y, px0.y, sh0.y), 0.f);
                v[2] = fmaxf(fmaf(sc0.z, px0.z, sh0.z), 0.f);
                v[3] = fmaxf(fmaf(sc0.w, px0.w, sh0.w), 0.f);
                v[4] = fmaxf(fmaf(sc1.x, px1.x, sh1.x), 0.f);
                v[5] = fmaxf(fmaf(sc1.y, px1.y, sh1.y), 0.f);
                v[6] = fmaxf(fmaf(sc1.z, px1.z, sh1.z), 0.f);
                v[7] = fmaxf(fmaf(sc1.w, px1.w, sh1.w), 0.f);
                float h0 = __bfloat162float(__float2bfloat16_rn(v[0]));
                float h1 = __bfloat162float(__float2bfloat16_rn(v[1]));
                float h2 = __bfloat162float(__float2bfloat16_rn(v[2]));
                float h3 = __bfloat162float(__float2bfloat16_rn(v[3]));
                float h4 = __bfloat162float(__float2bfloat16_rn(v[4]));
                float h5 = __bfloat162float(__float2bfloat16_rn(v[5]));
                float h6 = __bfloat162float(__float2bfloat16_rn(v[6]));
                float h7 = __bfloat162float(__float2bfloat16_rn(v[7]));
                uint4 u0 = make_uint4(packb(h0, h1), packb(h4, h5),
                                      packb(v[0] - h0, v[1] - h1), packb(v[4] - h4, v[5] - h5));
                uint4 u1 = make_uint4(packb(h2, h3), packb(h6, h7),
                                      packb(v[2] - h2, v[3] - h3), packb(v[6] - h6, v[7] - h7));
                char* dx = smem + (t & 1) * 8192 + row * 64;
                const int swz3 = (row >> 1) & 3;
                *(uint4*)(dx + (((grp * 2) ^ swz3) << 4)) = u0;
                *(uint4*)(dx + (((grp * 2 + 1) ^ swz3) << 4)) = u1;
            }
            if (t + 2 < TK) {
                uint32_t sd = aB + ((t + 2) & 3) * 8192 + tid * 32;
                const char* gs = gA + (size_t)(t + 2) * 8192 + tid * 32;
                CP16(sd, gs); CP16(sd + 16, gs + 16);
            }
            CPC;
            if (!XRES && t + 1 < TK) {
                px0 = *(const float4*)(xsrc + (t + 1) * 16 + xo1);
                px1 = *(const float4*)(xsrc + (t + 1) * 16 + xo2);
            }
            CPW2;
            __syncthreads();
            // ---- MMA on k16 t ----
            const char* ab = smem + AOFF + (t & 3) * 8192;
            const char* xb = XRES ? (smem + t * 8192) : (smem + (t & 1) * 8192);
            uint32_t ah[2][4], al[2][4];
#pragma unroll
            for (int i = 0; i < 2; i++) {
                uint4 q1 = *(const uint4*)(ab + aoA[i][0]);
                uint4 q2 = *(const uint4*)(ab + aoA[i][1]);
                ah[i][0] = q1.x; ah[i][1] = q2.x; ah[i][2] = q1.y; ah[i][3] = q2.y;
                al[i][0] = q1.z; al[i][1] = q2.z; al[i][2] = q1.w; al[i][3] = q2.w;
            }
            // double-buffered j loop, one LDS.128 per fragment
            {
                uint4 qb0 = *(const uint4*)(xb + boB[0]);
#pragma unroll
                for (int j = 0; j < 8; j++) {
                    uint4 qb1 = qb0;
                    if (j < 7) qb1 = *(const uint4*)(xb + boB[j + 1]);
#pragma unroll
                    for (int i = 0; i < 2; i++) {
                        mma16(c[i][j], ah[i], qb0.z, qb0.w);
                        uint32_t alf[4] = {al[i][0], al[i][1], al[i][2], al[i][3]};
                        mma16(c[i][j], alf, qb0.x, qb0.y);
                        mma16(c[i][j], ah[i], qb0.x, qb0.y);
                    }
                    qb0 = qb1;
                }
            }
        }

        // ---- epilogue: bias, stats (+max) ----
#pragma unroll
        for (int i = 0; i < 2; i++) {
            const int chA = mc * 128 + m0 + i * 16 + gq;
            const int chB = chA + 8;
            const float bvA = COLBIAS ? colbias[bb * Mtot + chA] : bias[chA];
            const float bvB = COLBIAS ? colbias[bb * Mtot + chB] : bias[chB];
            float sA = 0.f, qA = 0.f, sB = 0.f, qB = 0.f;
            float mA = -3.4e38f, mB = -3.4e38f;
#pragma unroll
            for (int j = 0; j < 8; j++) {
                c[i][j][0] += bvA; c[i][j][1] += bvA;
                c[i][j][2] += bvB; c[i][j][3] += bvB;
                sA += c[i][j][0] + c[i][j][1];
                qA = fmaf(c[i][j][0], c[i][j][0], qA);
                qA = fmaf(c[i][j][1], c[i][j][1], qA);
                sB += c[i][j][2] + c[i][j][3];
                qB = fmaf(c[i][j][2], c[i][j][2], qB);
                qB = fmaf(c[i][j][3], c[i][j][3], qB);
                if (DOMAX) {
                    mA = fmaxf(mA, fmaxf(c[i][j][0], c[i][j][1]));
                    mB = fmaxf(mB, fmaxf(c[i][j][2], c[i][j][3]));
                }
            }
#pragma unroll
            for (int o = 1; o <= 2; o <<= 1) {
                sA += __shfl_xor_sync(0xffffffffu, sA, o);
                qA += __shfl_xor_sync(0xffffffffu, qA, o);
                sB += __shfl_xor_sync(0xffffffffu, sB, o);
                qB += __shfl_xor_sync(0xffffffffu, qB, o);
                if (DOMAX) {
                    mA = fmaxf(mA, __shfl_xor_sync(0xffffffffu, mA, o));
                    mB = fmaxf(mB, __shfl_xor_sync(0xffffffffu, mB, o));
                }
            }
            if (t4 == 0) {
                atomicAdd(&d_sum[statoff + chA], sA);
                atomicAdd(&d_sq[statoff + chA], qA);
                atomicAdd(&d_sum[statoff + chB], sB);
                atomicAdd(&d_sq[statoff + chB], qB);
                if (DOMAX) {
                    unsigned uA = __float_as_uint(mA);
                    uA = (uA >> 31) ? ~uA : (uA | 0x80000000u);
                    atomicMax(&d_gmax[bb * Mtot + chA], uA);
                    unsigned uB = __float_as_uint(mB);
                    uB = (uB >> 31) ? ~uB : (uB | 0x80000000u);
                    atomicMax(&d_gmax[bb * Mtot + chB], uB);
                }
            }
        }

        if (STORE) {  // 32-col slabs through S (overlays A ring)
#pragma unroll
            for (int s = 0; s < 4; s++) {
                __syncthreads();
                if ((wid >> 2) == (s >> 1)) {
                    const int jb = (s & 1) * 4;
#pragma unroll
                    for (int i = 0; i < 2; i++)
#pragma unroll
                        for (int jj = 0; jj < 4; jj++) {
                            const int j = jb + jj;
                            const int lc = j * 8 + t4 * 2 - (s & 1) * 32;
                            const int chl = m0 + i * 16 + gq;
                            S[lc * 132 + chl] = c[i][j][0];
                            S[(lc + 1) * 132 + chl] = c[i][j][1];
                            S[lc * 132 + chl + 8] = c[i][j][2];
                            S[(lc + 1) * 132 + chl + 8] = c[i][j][3];
                        }
                }
                __syncthreads();
                const int lcol = tid >> 3;
                const int cg2 = (tid & 7) * 16;
                float* yp = Y + (size_t)(col0 + s * 32 + lcol) * Mtot + mc * 128 + cg2;
                const float* sp = S + lcol * 132 + cg2;
#pragma unroll
                for (int q = 0; q < 4; q++)
                    *(float4*)(yp + q * 4) = *(const float4*)(sp + q * 4);
            }
        }
    }
}

// decode max + inline conv3 BN finalize
__global__ void gbn_kernel(const float* __restrict__ g, const float* __restrict__ be) {
    int i = blockIdx.x * 256 + threadIdx.x;
    unsigned u = d_gmax[i];
    float f = (u >> 31) ? __uint_as_float(u & 0x7FFFFFFFu) : __uint_as_float(~u);
    int c = i & 1023;
    float m = d_sum[OFF3 + c] * (1.0f / NCOL);
    float v = d_sq[OFF3 + c] * (1.0f / NCOL) - m * m;
    float sc = g[c] * rsqrtf(v + 1e-5f);
    d_gbn[i] = fmaf(sc, f, fmaf(-m, sc, be[c]));
}

__global__ void hvec_kernel(const float* __restrict__ w1, const float* __restrict__ b1) {
    int bbk = blockIdx.x;
    int oc = blockIdx.y * 128 + threadIdx.x;
    __shared__ float gb[1024];
    for (int i = threadIdx.x; i < 1024; i += 128) gb[i] = d_gbn[bbk * 1024 + i];
    __syncthreads();
    float a = b1[oc];
    const float* wr = w1 + (size_t)oc * 1088;
#pragma unroll 4
    for (int k = 0; k < 1024; k++) a = fmaf(wr[k], gb[k], a);
    d_hvec[bbk * 512 + oc] = a;
}

// h4 with inline h3 BN finalize
__global__ void h4_kernel(const float* __restrict__ w4, const float* __restrict__ b4,
                          const float* __restrict__ g, const float* __restrict__ be,
                          float* __restrict__ out) {
    __shared__ float ws[128], scs[128], shs[128];
    __shared__ int vcnt;
    int tid = threadIdx.x;
    if (tid < 128) {
        ws[tid] = w4[tid];
        float m = d_sum[OFFH3 + tid] * (1.0f / NCOL);
        float v = d_sq[OFFH3 + tid] * (1.0f / NCOL) - m * m;
        float sc = g[tid] * rsqrtf(v + 1e-5f);
        scs[tid] = sc;
        shs[tid] = fmaf(-m, sc, be[tid]);
    }
    if (tid == 0) vcnt = 0;
    __syncthreads();
    int wid = tid >> 5, lid = tid & 31;
    int col = blockIdx.x * 8 + wid;
    const float* src = d_rawh3 + (size_t)col * 128;
    float a = 0.f;
#pragma unroll
    for (int c = 0; c < 4; c++) {
        int k = c * 32 + lid;
        float v = src[k];
        a = fmaf(ws[k], fmaxf(fmaf(scs[k], v, shs[k]), 0.f), a);
    }
#pragma unroll
    for (int o = 16; o >= 1; o >>= 1) a += __shfl_xor_sync(0xffffffffu, a, o);
    if (lid == 0) {
        float wv = 1.f + a + __ldg(b4);
        out[96 + col] = wv;
        if (wv > 1e-4f) atomicAdd(&vcnt, 1);
    }
    __syncthreads();
    if (tid == 0) atomicAdd(&d_nv[(blockIdx.x * 8) >> 11], vcnt);
}

__global__ void solve_kernel(const float* __restrict__ pts, float* __restrict__ out) {
    int bbk = blockIdx.x;
    const float* w = out + 96 + bbk * NPTS;
    const float* px = pts + (size_t)bbk * 3 * NPTS;
    bool usew = d_nv[bbk] > 3;
    float acc[9];
#pragma unroll
    for (int k = 0; k < 9; k++) acc[k] = 0.f;
    for (int n = threadIdx.x; n < NPTS; n += 256) {
        float wv = w[n];
        float we = usew ? ((wv > 1e-4f) ? wv : 0.f) : 1.f;
        float x = px[n], y = px[NPTS + n], z = px[2 * NPTS + n];
        acc[0] = fmaf(we * x, x, acc[0]);
        acc[1] = fmaf(we * x, y, acc[1]);
        acc[2] += we * x;
        acc[3] = fmaf(we * y, y, acc[3]);
        acc[4] += we * y;
        acc[5] += we;
        acc[6] = fmaf(we * x, z, acc[6]);
        acc[7] = fmaf(we * y, z, acc[7]);
        acc[8] = fmaf(we, z, acc[8]);
    }
#pragma unroll
    for (int k = 0; k < 9; k++)
#pragma unroll
        for (int o = 16; o >= 1; o >>= 1) acc[k] += __shfl_xor_sync(0xffffffffu, acc[k], o);
    __shared__ float red[8][9];
    int wid = threadIdx.x >> 5, lane = threadIdx.x & 31;
    if (lane == 0)
        for (int k = 0; k < 9; k++) red[wid][k] = acc[k];
    __syncthreads();
    if (threadIdx.x == 0) {
        float a[9];
        for (int k = 0; k < 9; k++) {
            float s = 0.f;
            for (int i = 0; i < 8; i++) s += red[i][k];
            a[k] = s;
        }
        float L11 = sqrtf(a[0]);
        float L21 = a[1] / L11, L31 = a[2] / L11;
        float L22 = sqrtf(a[3] - L21 * L21);
        float L32 = (a[4] - L31 * L21) / L22;
        float L33 = sqrtf(a[5] - L31 * L31 - L32 * L32);
        float y1 = a[6] / L11;
        float y2 = (a[7] - L21 * y1) / L22;
        float y3 = (a[8] - L31 * y1 - L32 * y2) / L33;
        float be3 = y3 / L33;
        float be2 = (y2 - L32 * be3) / L22;
        float be1 = (y1 - L21 * be2 - L31 * be3) / L11;
        out[bbk * 3 + 0] = be1;
        out[bbk * 3 + 1] = be2;
        out[bbk * 3 + 2] = be3;
    }
}

// ================= launch =================
extern "C" void kernel_launch(void* const* d_in, const int* in_sizes, int n_in,
                              void* d_out, int out_size) {
    const float* pts = (const float*)d_in[0];
    const float* e_w1 = (const float*)d_in[1];
    const float* e_b1 = (const float*)d_in[2];
    const float* e_g1 = (const float*)d_in[3];
    const float* e_be1 = (const float*)d_in[4];
    const float* e_w2 = (const float*)d_in[5];
    const float* e_b2 = (const float*)d_in[6];
    const float* e_g2 = (const float*)d_in[7];
    const float* e_be2 = (const float*)d_in[8];
    const float* e_w3 = (const float*)d_in[9];
    const float* e_b3 = (const float*)d_in[10];
    const float* e_g3 = (const float*)d_in[11];
    const float* e_be3 = (const float*)d_in[12];
    const float* h_w1 = (const float*)d_in[13];
    const float* h_b1 = (const float*)d_in[14];
    const float* h_g1 = (const float*)d_in[15];
    const float* h_be1 = (const float*)d_in[16];
    const float* h_w2 = (const float*)d_in[17];
    const float* h_b2 = (const float*)d_in[18];
    const float* h_g2 = (const float*)d_in[19];
    const float* h_be2 = (const float*)d_in[20];
    const float* h_w3 = (const float*)d_in[21];
    const float* h_b3 = (const float*)d_in[22];
    const float* h_g3 = (const float*)d_in[23];
    const float* h_be3 = (const float*)d_in[24];
    const float* h_w4 = (const float*)d_in[25];
    const float* h_b4 = (const float*)d_in[26];
    float* out = (float*)d_out;

    float *p_raw1, *p_raw2, *p_rawh1, *p_rawh2, *p_rawh3, *p_hvec;
    char* p_wpl;
    cudaGetSymbolAddress((void**)&p_raw1, d_raw1);
    cudaGetSymbolAddress((void**)&p_raw2, d_raw2);
    cudaGetSymbolAddress((void**)&p_rawh1, d_rawh1);
    cudaGetSymbolAddress((void**)&p_rawh2, d_rawh2);
    cudaGetSymbolAddress((void**)&p_rawh3, d_rawh3);
    cudaGetSymbolAddress((void**)&p_hvec, d_hvec);
    cudaGetSymbolAddress((void**)&p_wpl, d_wpl);

    cudaFuncSetAttribute((const void*)mma_kernel<true, true, false, false, 4, 1>,
                         cudaFuncAttributeMaxDynamicSharedMemorySize, 66048);
    cudaFuncSetAttribute((const void*)mma_kernel<true, false, true, false, 8, 8>,
                         cudaFuncAttributeMaxDynamicSharedMemorySize, 99328);
    cudaFuncSetAttribute((const void*)mma_kernel<true, true, false, true, 4, 4>,
                         cudaFuncAttributeMaxDynamicSharedMemorySize, 66048);
    cudaFuncSetAttribute((const void*)mma_kernel<false, true, false, false, 32, 2>,
                         cudaFuncAttributeMaxDynamicSharedMemorySize, 53248);
    cudaFuncSetAttribute((const void*)mma_kernel<false, true, false, false, 16, 1>,
                         cudaFuncAttributeMaxDynamicSharedMemorySize, 51200);

    prep_kernel<<<128, 256>>>(e_w2, e_w3, h_w1, h_w2, h_w3, p_wpl);
    conv1_kernel<<<256, 256>>>(pts, e_w1, e_b1);
    // conv2: 128 x 65536 x 64 (XRES)
    mma_kernel<true, true, false, false, 4, 1><<<512, 256, 66048>>>(
        p_wpl + WOFF_C2, e_b2, e_g1, e_be1, p_raw1, OFF1, p_raw2, OFF2, nullptr);
    // conv3: 1024 x 65536 x 128 (XRES, stats+max only)
    mma_kernel<true, false, true, false, 8, 8><<<512, 256, 99328>>>(
        p_wpl + WOFF_C3, e_b3, e_g2, e_be2, p_raw2, OFF2, nullptr, OFF3, nullptr);
    gbn_kernel<<<128, 256>>>(e_g3, e_be3);
    hvec_kernel<<<dim3(32, 4), 128>>>(h_w1, h_b1);
    // h1 (pointfeat): 512 x 65536 x 64 (XRES, colbias)
    mma_kernel<true, true, false, true, 4, 4><<<512, 256, 66048>>>(
        p_wpl + WOFF_H1, h_b1, e_g1, e_be1, p_raw1, OFF1, p_rawh1, OFFH1, p_hvec);
    // h2: 256 x 65536 x 512 (streaming)
    mma_kernel<false, true, false, false, 32, 2><<<512, 256, 53248>>>(
        p_wpl + WOFF_H2, h_b2, h_g1, h_be1, p_rawh1, OFFH1, p_rawh2, OFFH2, nullptr);
    // h3: 128 x 65536 x 256 (streaming)
    mma_kernel<false, true, false, false, 16, 1><<<512, 256, 51200>>>(
        p_wpl + WOFF_H3, h_b3, h_g2, h_be2, p_rawh2, OFFH2, p_rawh3, OFFH3, nullptr);
    h4_kernel<<<8192, 256>>>(h_w4, h_b4, h_g3, h_be3, out);
    solve_kernel<<<32, 256>>>(pts, out);
}